// round 4
// baseline (speedup 1.0000x reference)
#include <cuda_runtime.h>
#include <cstdint>

namespace {
constexpr int kB   = 256;
constexpr int kD   = 2048;
constexpr int kS   = 8;
constexpr int kOut = 1000;

constexpr int BM = 32;                 // rows per m-tile
constexpr int BN = 128;                // cols per block
constexpr int BK = 16;                 // K per pipeline stage
constexpr int NSPLIT = 8;
constexpr int KSPLIT = kD / NSPLIT;    // 256
constexpr int NSTG   = KSPLIT / BK;    // 16 stages per block
constexpr int STAGES = 4;              // smem ring depth (3-ahead)
constexpr int MT = 4;                  // m-tiles per subject (covers counts<=128)
constexpr int XPAD = 20;               // X row stride in floats (80B: 16B-mult, bank-skew)
constexpr int NTILES = (kOut + BN - 1) / BN;  // 8
}

// ---- packed f32x2 helpers ----
__device__ __forceinline__ void ffma2(unsigned long long& d,
                                      unsigned long long a, unsigned long long b) {
    asm("fma.rn.f32x2 %0, %1, %2, %0;" : "+l"(d) : "l"(a), "l"(b));
}
__device__ __forceinline__ unsigned long long dup2(float v) {
    unsigned long long r;
    asm("mov.b64 %0, {%1, %1};" : "=l"(r) : "f"(v));
    return r;
}
__device__ __forceinline__ unsigned long long pack2(float lo, float hi) {
    unsigned long long r;
    asm("mov.b64 %0, {%1, %2};" : "=l"(r) : "f"(lo), "f"(hi));
    return r;
}
__device__ __forceinline__ void unpack2(unsigned long long v, float& lo, float& hi) {
    asm("mov.b64 {%0, %1}, %2;" : "=f"(lo), "=f"(hi) : "l"(v));
}

// ---- cp.async helpers ----
__device__ __forceinline__ unsigned smem_u32(const void* p) {
    return (unsigned)__cvta_generic_to_shared(p);
}
__device__ __forceinline__ void cp16(unsigned dst, const void* src, int src_sz) {
    asm volatile("cp.async.cg.shared.global [%0], [%1], 16, %2;"
                 :: "r"(dst), "l"(src), "r"(src_sz) : "memory");
}
__device__ __forceinline__ void cp_commit() {
    asm volatile("cp.async.commit_group;" ::: "memory");
}
__device__ __forceinline__ void cp_wait2() {
    asm volatile("cp.async.wait_group 2;" ::: "memory");
}

// ---------------------------------------------------------------------------
// Init: out[b, :] = bias[sid[b], :]   (gemm then atomically accumulates)
// ---------------------------------------------------------------------------
__global__ __launch_bounds__(256) void init_out_kernel(
    const unsigned int* __restrict__ sid_words,
    const float* __restrict__ bias,
    float* __restrict__ out)
{
    __shared__ int i32_flag;
    if (threadIdx.x == 0) i32_flag = 0;
    __syncthreads();
    if (threadIdx.x < 128 && sid_words[2 * threadIdx.x + 1] != 0u)
        atomicOr(&i32_flag, 1);
    __syncthreads();

    const int q = blockIdx.x * blockDim.x + threadIdx.x;
    const int base = q * 4;
    if (base >= kB * kOut) return;
    const int b = base / kOut;
    const int n = base - b * kOut;        // kOut % 4 == 0: quad stays in row
    const int sb = i32_flag ? (int)sid_words[b] : (int)sid_words[2 * b];
    *reinterpret_cast<float4*>(out + base) =
        *reinterpret_cast<const float4*>(bias + (size_t)sb * kOut + n);
}

// ---------------------------------------------------------------------------
// GEMM: grid (n_tile=8, subject=8, mt*split=32), 128 threads.
// cp.async 4-stage ring, packed-f32x2 compute (pack along M), REDG epilogue.
// ---------------------------------------------------------------------------
__global__ __launch_bounds__(128) void gemm_kernel(
    const float* __restrict__ x,              // [B, D]
    const float* __restrict__ W,              // [S, D, OUT]
    const unsigned int* __restrict__ sid_words,
    float* __restrict__ out)                  // [B, OUT] (bias pre-added)
{
    const int s     = blockIdx.y;
    const int mt    = blockIdx.z & (MT - 1);
    const int split = blockIdx.z / MT;
    const int m0    = mt * BM;
    const int n0    = blockIdx.x * BN;
    const int kbase = split * KSPLIT;
    const int t     = threadIdx.x;

    __shared__ float Xs[STAGES][BM][XPAD];   // X tile stored [m][k]
    __shared__ float Ws[STAGES][BK][BN];
    __shared__ int   srows[BM];
    __shared__ int   cnt_sh;

    // ---- in-block bucketing (warp 0): ordered row list for subject s ----
    if (t < BM) srows[t] = -1;
    if (t < 32) {
        const unsigned full = 0xFFFFFFFFu;
        unsigned any_hi = 0;
        #pragma unroll
        for (int c = 0; c < 4; ++c) any_hi |= sid_words[2 * (c * 32 + t) + 1];
        const bool is_i32 = __any_sync(full, any_hi != 0u);
        int base = 0;
        #pragma unroll
        for (int c = 0; c < 8; ++c) {
            const int b  = c * 32 + t;
            const int sb = is_i32 ? (int)sid_words[b] : (int)sid_words[2 * b];
            const unsigned m = __ballot_sync(full, sb == s);
            if (sb == s) {
                const int pos = base + __popc(m & ((1u << t) - 1u));
                if (pos >= m0 && pos < m0 + BM) srows[pos - m0] = b;
            }
            base += __popc(m);
        }
        if (t == 0) cnt_sh = base;
    }
    __syncthreads();
    if (m0 >= cnt_sh) return;   // uniform exit for empty tiles

    // ---- cp.async source roles ----
    // X: 32m x 16k floats = 128 x 16B chunks, one per thread.
    const int xm = t >> 2;            // 0..31
    const int xq = (t & 3) * 4;       // k quad within stage
    const int xrow = srows[xm];
    const float* xsrc0 = x + (size_t)(xrow < 0 ? 0 : xrow) * kD + kbase + xq;
    const int xsz = (xrow < 0) ? 0 : 16;
    const unsigned xdst0 = smem_u32(&Xs[0][xm][xq]);

    // W: 16k x 128n floats = 512 chunks, four per thread (k-rows t>>5 + 4q).
    const int wk = t >> 5;            // 0..3
    const int wn = (t & 31) * 4;      // 0..124
    const float* wsrc0 = W + ((size_t)s * kD + kbase + wk) * kOut + n0 + wn;
    const int wsz = (n0 + wn + 3 < kOut) ? 16 : 0;   // zero-fill OOB n-tail
    const unsigned wdst0 = smem_u32(&Ws[0][wk][wn]);

    constexpr unsigned XSTAGE = BM * XPAD * 4;       // bytes per X stage
    constexpr unsigned WSTAGE = BK * BN * 4;         // bytes per W stage

    auto issue_stage = [&](int st) {
        if (st < NSTG) {
            const int buf = st & (STAGES - 1);
            cp16(xdst0 + buf * XSTAGE, xsrc0 + st * BK, xsz);
            const float* wsrc = wsrc0 + (size_t)st * BK * kOut;
            #pragma unroll
            for (int q = 0; q < 4; ++q)
                cp16(wdst0 + buf * WSTAGE + q * 4 * BN * 4,
                     wsrc + (size_t)q * 4 * kOut, wsz);
        }
        cp_commit();   // empty groups at the tail keep wait counts aligned
    };

    issue_stage(0);
    issue_stage(1);
    issue_stage(2);

    // ---- compute roles: rows [tm, tm+4), cols [tn, tn+8) ----
    const int ty = t >> 4;            // 0..7
    const int tx = t & 15;            // 0..15
    const int tm = ty * 4;
    const int tn = tx * 8;

    // accLo[p][j]: m-pair p (rows tm+2p, tm+2p+1), col tn+j     (j=0..3)
    // accHi[p][j]: same m-pair, col tn+4+j
    unsigned long long accLo[2][4], accHi[2][4];
    #pragma unroll
    for (int p = 0; p < 2; ++p)
        #pragma unroll
        for (int j = 0; j < 4; ++j) { accLo[p][j] = 0ull; accHi[p][j] = 0ull; }

    for (int st = 0; st < NSTG; ++st) {
        cp_wait2();
        __syncthreads();
        const int buf = st & (STAGES - 1);
        const float* Xb = &Xs[buf][0][0];
        const float* Wb = &Ws[buf][0][0];
        #pragma unroll
        for (int kk = 0; kk < BK; ++kk) {
            const unsigned long long xm01 =
                pack2(Xb[(tm + 0) * XPAD + kk], Xb[(tm + 1) * XPAD + kk]);
            const unsigned long long xm23 =
                pack2(Xb[(tm + 2) * XPAD + kk], Xb[(tm + 3) * XPAD + kk]);
            const float4 w0 = *reinterpret_cast<const float4*>(Wb + kk * BN + tn);
            const float4 w1 = *reinterpret_cast<const float4*>(Wb + kk * BN + tn + 4);
            const unsigned long long d0 = dup2(w0.x), d1 = dup2(w0.y),
                                     d2 = dup2(w0.z), d3 = dup2(w0.w);
            const unsigned long long d4 = dup2(w1.x), d5 = dup2(w1.y),
                                     d6 = dup2(w1.z), d7 = dup2(w1.w);
            ffma2(accLo[0][0], xm01, d0);  ffma2(accLo[1][0], xm23, d0);
            ffma2(accLo[0][1], xm01, d1);  ffma2(accLo[1][1], xm23, d1);
            ffma2(accLo[0][2], xm01, d2);  ffma2(accLo[1][2], xm23, d2);
            ffma2(accLo[0][3], xm01, d3);  ffma2(accLo[1][3], xm23, d3);
            ffma2(accHi[0][0], xm01, d4);  ffma2(accHi[1][0], xm23, d4);
            ffma2(accHi[0][1], xm01, d5);  ffma2(accHi[1][1], xm23, d5);
            ffma2(accHi[0][2], xm01, d6);  ffma2(accHi[1][2], xm23, d6);
            ffma2(accHi[0][3], xm01, d7);  ffma2(accHi[1][3], xm23, d7);
        }
        issue_stage(st + 3);
        __syncthreads();
    }

    // ---- epilogue: REDG accumulate into out (bias already there) ----
    #pragma unroll
    for (int i = 0; i < 4; ++i) {
        const int r = srows[tm + i];
        if (r < 0) continue;
        const int p   = i >> 1;       // m-pair index
        const int lane = i & 1;       // lo/hi within pair
        float v[8];
        #pragma unroll
        for (int j = 0; j < 4; ++j) {
            float lo, hi;
            unpack2(accLo[p][j], lo, hi);
            v[j] = lane ? hi : lo;
            unpack2(accHi[p][j], lo, hi);
            v[4 + j] = lane ? hi : lo;
        }
        float* prow = out + (size_t)r * kOut;
        #pragma unroll
        for (int h = 0; h < 8; h += 4) {
            const int n = n0 + tn + h;
            if (n + 3 < kOut) {       // kOut%4==0: quad fully in or out
                atomicAdd(prow + n + 0, v[h + 0]);
                atomicAdd(prow + n + 1, v[h + 1]);
                atomicAdd(prow + n + 2, v[h + 2]);
                atomicAdd(prow + n + 3, v[h + 3]);
            }
        }
    }
}

extern "C" void kernel_launch(void* const* d_in, const int* in_sizes, int n_in,
                              void* d_out, int out_size) {
    const float*        x   = (const float*)d_in[0];
    const unsigned int* sid = (const unsigned int*)d_in[1];
    const float*        W   = (const float*)d_in[2];
    const float*        b   = (const float*)d_in[3];
    float*              out = (float*)d_out;

    const int nq = (kB * kOut) / 4;   // 64000 quads
    init_out_kernel<<<nq / 256, 256>>>(sid, b, out);
    dim3 grid(NTILES, kS, MT * NSPLIT);   // (8, 8, 32)
    gemm_kernel<<<grid, 128>>>(x, W, sid, out);
}

// round 5
// speedup vs baseline: 1.7130x; 1.7130x over previous
#include <cuda_runtime.h>
#include <cstdint>

namespace {
constexpr int kB   = 256;
constexpr int kD   = 2048;
constexpr int kS   = 8;
constexpr int kOut = 1000;

constexpr int BM = 32;                 // rows per m-tile
constexpr int BN = 256;                // cols per block
constexpr int BK = 16;                 // K per pipeline stage
constexpr int NSPLIT = 8;
constexpr int KSPLIT = kD / NSPLIT;    // 256
constexpr int NSTG   = KSPLIT / BK;    // 16 stages per block
constexpr int MT = 4;                  // m-tiles per subject (covers counts <= 128)
constexpr int XPAD = 36;               // X k-row stride (16B multiple, bank skew)
constexpr int NTILES = (kOut + BN - 1) / BN;  // 4
}

// Device scratch (allocations forbidden in kernel_launch)
__device__ float g_partial[NSPLIT * kB * kOut];   // 8 MB

// ---- packed f32x2 helpers ----
__device__ __forceinline__ void ffma2(unsigned long long& d,
                                      unsigned long long a, unsigned long long b) {
    asm("fma.rn.f32x2 %0, %1, %2, %0;" : "+l"(d) : "l"(a), "l"(b));
}
__device__ __forceinline__ unsigned long long dup2(float v) {
    unsigned long long r;
    asm("mov.b64 %0, {%1, %1};" : "=l"(r) : "f"(v));
    return r;
}
__device__ __forceinline__ void unpack2(unsigned long long v, float& lo, float& hi) {
    asm("mov.b64 {%0, %1}, %2;" : "=f"(lo), "=f"(hi) : "l"(v));
}

// ---- cp.async helpers ----
__device__ __forceinline__ unsigned smem_u32(const void* p) {
    return (unsigned)__cvta_generic_to_shared(p);
}
__device__ __forceinline__ void cp16(unsigned dst, const void* src, int src_sz) {
    asm volatile("cp.async.cg.shared.global [%0], [%1], 16, %2;"
                 :: "r"(dst), "l"(src), "r"(src_sz) : "memory");
}
__device__ __forceinline__ void cp_commit() {
    asm volatile("cp.async.commit_group;" ::: "memory");
}
__device__ __forceinline__ void cp_wait1() {
    asm volatile("cp.async.wait_group 1;" ::: "memory");
}

// ---------------------------------------------------------------------------
// GEMM: grid (n_tile=4, subject=8, mt(4)*split(8)=32), 128 threads.
// Thread tile 8m x 8n. Accumulators packed along N -> W operands come
// directly from LDS.128 as packed pairs; X read broadcast from [k][m] smem.
// W via cp.async 2-stage ring; X via reg-staged LDG + transpose STS.
// ---------------------------------------------------------------------------
__global__ __launch_bounds__(128, 4) void gemm_kernel(
    const float* __restrict__ x,              // [B, D]
    const float* __restrict__ W,              // [S, D, OUT]
    const unsigned int* __restrict__ sid_words)
{
    const int s     = blockIdx.y;
    const int mt    = blockIdx.z & (MT - 1);
    const int split = blockIdx.z >> 2;        // MT = 4
    const int m0    = mt * BM;
    const int n0    = blockIdx.x * BN;
    const int kbase = split * KSPLIT;
    const int t     = threadIdx.x;

    __shared__ __align__(16) float Xs[2][BK][XPAD];  // X tile [k][m]
    __shared__ __align__(16) float Ws[2][BK][BN];
    __shared__ int srows[BM];
    __shared__ int cnt_sh;

    // ---- in-block bucketing (warp 0): ordered row list for subject s ----
    // int64-vs-int32 detection: for little-endian int64 ids in [0,8) all odd
    // 32-bit words of the first 256 words are zero.
    if (t < BM) srows[t] = -1;
    if (t < 32) {
        const unsigned full = 0xFFFFFFFFu;
        unsigned any_hi = 0;
        #pragma unroll
        for (int c = 0; c < 4; ++c) any_hi |= sid_words[2 * (c * 32 + t) + 1];
        const bool is_i32 = __any_sync(full, any_hi != 0u);
        int base = 0;
        #pragma unroll
        for (int c = 0; c < 8; ++c) {
            const int b  = c * 32 + t;
            const int sb = is_i32 ? (int)sid_words[b] : (int)sid_words[2 * b];
            const unsigned m = __ballot_sync(full, sb == s);
            if (sb == s) {
                const int pos = base + __popc(m & ((1u << t) - 1u));
                if (pos >= m0 && pos < m0 + BM) srows[pos - m0] = b;
            }
            base += __popc(m);
        }
        if (t == 0) cnt_sh = base;
    }
    __syncthreads();
    if (m0 >= cnt_sh) return;   // uniform exit for empty tiles

    // ---- W cp.async roles: 1024 16B chunks per stage, 8 per thread ----
    const int wn_   = (t & 63) * 4;        // col within tile (0..252)
    const int khalf = t >> 6;              // 0/1
    const float* wbase = W + ((size_t)s * kD + kbase) * kOut + n0 + wn_;
    const int wsz = (n0 + wn_ + 3 < kOut) ? 16 : 0;   // zero-fill OOB n-tail

    auto issueW = [&](int st) {
        if (st < NSTG) {
            const int buf = st & 1;
            const float* wsrc = wbase + (size_t)st * BK * kOut;
            #pragma unroll
            for (int q = 0; q < 8; ++q) {
                const int k = 2 * q + khalf;
                cp16(smem_u32(&Ws[buf][k][wn_]), wsrc + (size_t)k * kOut, wsz);
            }
        }
        cp_commit();   // empty tail groups keep wait counts aligned
    };

    // ---- X roles: 128 k-quads per stage, 1 LDG.128 + 4 STS per thread ----
    const int xm_  = t >> 2;               // 0..31
    const int xk4  = (t & 3) * 4;          // k quad within stage
    const int xrow = srows[xm_];
    const float* xptr = (xrow >= 0) ? (x + (size_t)xrow * kD + kbase + xk4)
                                    : nullptr;
    float4 xr = make_float4(0.f, 0.f, 0.f, 0.f);

    issueW(0);
    issueW(1);
    if (xptr) xr = *reinterpret_cast<const float4*>(xptr);   // stage 0

    // ---- compute roles: rows [tm, tm+8), cols [tn, tn+8) ----
    const int tm = (t >> 5) * 8;           // uniform per warp -> broadcast LDS
    const int tn = (t & 31) * 8;

    unsigned long long acc[8][4];          // [m][n-pair]
    #pragma unroll
    for (int i = 0; i < 8; ++i)
        #pragma unroll
        for (int j = 0; j < 4; ++j) acc[i][j] = 0ull;

    for (int st = 0; st < NSTG; ++st) {
        const int buf = st & 1;
        cp_wait1();                         // W(st) arrived
        // transpose-store X(st)
        Xs[buf][xk4 + 0][xm_] = xr.x;
        Xs[buf][xk4 + 1][xm_] = xr.y;
        Xs[buf][xk4 + 2][xm_] = xr.z;
        Xs[buf][xk4 + 3][xm_] = xr.w;
        __syncthreads();
        // prefetch X(st+1) into registers
        if (st + 1 < NSTG && xptr)
            xr = *reinterpret_cast<const float4*>(xptr + (st + 1) * BK);

        #pragma unroll
        for (int kk = 0; kk < BK; ++kk) {
            const float4 xa = *reinterpret_cast<const float4*>(&Xs[buf][kk][tm]);
            const float4 xb = *reinterpret_cast<const float4*>(&Xs[buf][kk][tm + 4]);
            const ulonglong2 wA = *reinterpret_cast<const ulonglong2*>(&Ws[buf][kk][tn]);
            const ulonglong2 wB = *reinterpret_cast<const ulonglong2*>(&Ws[buf][kk][tn + 4]);
            const unsigned long long dx[8] = {
                dup2(xa.x), dup2(xa.y), dup2(xa.z), dup2(xa.w),
                dup2(xb.x), dup2(xb.y), dup2(xb.z), dup2(xb.w)};
            #pragma unroll
            for (int i = 0; i < 8; ++i) {
                ffma2(acc[i][0], dx[i], wA.x);
                ffma2(acc[i][1], dx[i], wA.y);
                ffma2(acc[i][2], dx[i], wB.x);
                ffma2(acc[i][3], dx[i], wB.y);
            }
        }
        __syncthreads();                    // all reads of Wbuf[buf] done
        issueW(st + 2);                     // refill into Wbuf[buf]
    }

    // ---- epilogue: write split partials (reduce adds bias) ----
    float* pbase = g_partial + (size_t)split * kB * kOut;
    #pragma unroll
    for (int i = 0; i < 8; ++i) {
        const int r = srows[tm + i];
        if (r < 0) continue;
        float v[8];
        #pragma unroll
        for (int j = 0; j < 4; ++j) unpack2(acc[i][j], v[2 * j], v[2 * j + 1]);
        float* prow = pbase + (size_t)r * kOut;
        const int n = n0 + tn;
        if (n + 3 < kOut)
            *reinterpret_cast<float4*>(prow + n) = make_float4(v[0], v[1], v[2], v[3]);
        if (n + 7 < kOut)
            *reinterpret_cast<float4*>(prow + n + 4) = make_float4(v[4], v[5], v[6], v[7]);
    }
}

// ---------------------------------------------------------------------------
// Reduce: out = sum of split partials + per-subject bias (float4).
// ---------------------------------------------------------------------------
__global__ __launch_bounds__(256) void reduce_kernel(
    const unsigned int* __restrict__ sid_words,
    const float* __restrict__ bias,   // [S, OUT]
    float* __restrict__ out)          // [B, OUT]
{
    __shared__ int i32_flag;
    if (threadIdx.x == 0) i32_flag = 0;
    __syncthreads();
    if (threadIdx.x < 128 && sid_words[2 * threadIdx.x + 1] != 0u)
        atomicOr(&i32_flag, 1);
    __syncthreads();

    const int q = blockIdx.x * blockDim.x + threadIdx.x;
    const int base = q * 4;
    if (base >= kB * kOut) return;
    const int b = base / kOut;
    const int n = base - b * kOut;        // kOut % 4 == 0: quad stays in row
    const int sb = i32_flag ? (int)sid_words[b] : (int)sid_words[2 * b];

    float4 v = *reinterpret_cast<const float4*>(bias + (size_t)sb * kOut + n);
    #pragma unroll
    for (int sp = 0; sp < NSPLIT; ++sp) {
        const float4 p = *reinterpret_cast<const float4*>(
            g_partial + (size_t)sp * kB * kOut + base);
        v.x += p.x; v.y += p.y; v.z += p.z; v.w += p.w;
    }
    *reinterpret_cast<float4*>(out + base) = v;
}

extern "C" void kernel_launch(void* const* d_in, const int* in_sizes, int n_in,
                              void* d_out, int out_size) {
    const float*        x   = (const float*)d_in[0];
    const unsigned int* sid = (const unsigned int*)d_in[1];
    const float*        W   = (const float*)d_in[2];
    const float*        b   = (const float*)d_in[3];
    float*              out = (float*)d_out;

    dim3 grid(NTILES, kS, MT * NSPLIT);   // (4, 8, 32)
    gemm_kernel<<<grid, 128>>>(x, W, sid);
    const int nq = (kB * kOut) / 4;       // 64000 quads
    reduce_kernel<<<(nq + 255) / 256, 256>>>(sid, b, out);
}

// round 6
// speedup vs baseline: 2.2356x; 1.3051x over previous
#include <cuda_runtime.h>
#include <cstdint>

namespace {
constexpr int kB   = 256;
constexpr int kD   = 2048;
constexpr int kS   = 8;
constexpr int kOut = 1000;

constexpr int BM = 32;                 // rows per m-tile
constexpr int BN = 256;                // cols per block
constexpr int BK = 16;                 // K per pipeline stage
constexpr int NSPLIT = 16;
constexpr int KSPLIT = kD / NSPLIT;    // 128
constexpr int NSTG   = KSPLIT / BK;    // 8 stages per block
constexpr int MT = 4;                  // m-tiles per subject (covers counts <= 128)
constexpr int XPAD = 36;               // X k-row stride (16B multiple, bank skew)
constexpr int NTILES = (kOut + BN - 1) / BN;  // 4
}

// Device scratch (allocations forbidden in kernel_launch)
__device__ float g_partial[NSPLIT * kB * kOut];   // 16 MB

// ---- packed f32x2 helpers ----
__device__ __forceinline__ void ffma2(unsigned long long& d,
                                      unsigned long long a, unsigned long long b) {
    asm("fma.rn.f32x2 %0, %1, %2, %0;" : "+l"(d) : "l"(a), "l"(b));
}
__device__ __forceinline__ unsigned long long dup2(float v) {
    unsigned long long r;
    asm("mov.b64 %0, {%1, %1};" : "=l"(r) : "f"(v));
    return r;
}
__device__ __forceinline__ void unpack2(unsigned long long v, float& lo, float& hi) {
    asm("mov.b64 {%0, %1}, %2;" : "=f"(lo), "=f"(hi) : "l"(v));
}

// ---- cp.async helpers ----
__device__ __forceinline__ unsigned smem_u32(const void* p) {
    return (unsigned)__cvta_generic_to_shared(p);
}
__device__ __forceinline__ void cp16(unsigned dst, const void* src, int src_sz) {
    asm volatile("cp.async.cg.shared.global [%0], [%1], 16, %2;"
                 :: "r"(dst), "l"(src), "r"(src_sz) : "memory");
}
__device__ __forceinline__ void cp_commit() {
    asm volatile("cp.async.commit_group;" ::: "memory");
}
__device__ __forceinline__ void cp_wait1() {
    asm volatile("cp.async.wait_group 1;" ::: "memory");
}

// ---------------------------------------------------------------------------
// GEMM: grid (n_tile=4, subject=8, mt(4)*split(16)=64), 128 threads.
// Thread tile 8m x 8n, accumulators packed along N (W pairs come straight
// from LDS.128). W via cp.async 2-stage ring; X reg-staged LDG + transpose.
// NSPLIT=16 -> ~740 active blocks (~5/SM) so LDS latency / barriers are
// covered and the fma pipe becomes the binder.
// ---------------------------------------------------------------------------
__global__ __launch_bounds__(128, 5) void gemm_kernel(
    const float* __restrict__ x,              // [B, D]
    const float* __restrict__ W,              // [S, D, OUT]
    const unsigned int* __restrict__ sid_words)
{
    const int s     = blockIdx.y;
    const int mt    = blockIdx.z & (MT - 1);
    const int split = blockIdx.z >> 2;        // MT = 4
    const int m0    = mt * BM;
    const int n0    = blockIdx.x * BN;
    const int kbase = split * KSPLIT;
    const int t     = threadIdx.x;

    __shared__ __align__(16) float Xs[2][BK][XPAD];  // X tile [k][m]
    __shared__ __align__(16) float Ws[2][BK][BN];
    __shared__ int srows[BM];
    __shared__ int cnt_sh;

    // ---- in-block bucketing (warp 0): ordered row list for subject s ----
    // int64-vs-int32 detection: for little-endian int64 ids in [0,8) all odd
    // 32-bit words of the first 256 words are zero.
    if (t < BM) srows[t] = -1;
    if (t < 32) {
        const unsigned full = 0xFFFFFFFFu;
        unsigned any_hi = 0;
        #pragma unroll
        for (int c = 0; c < 4; ++c) any_hi |= sid_words[2 * (c * 32 + t) + 1];
        const bool is_i32 = __any_sync(full, any_hi != 0u);
        int base = 0;
        #pragma unroll
        for (int c = 0; c < 8; ++c) {
            const int b  = c * 32 + t;
            const int sb = is_i32 ? (int)sid_words[b] : (int)sid_words[2 * b];
            const unsigned m = __ballot_sync(full, sb == s);
            if (sb == s) {
                const int pos = base + __popc(m & ((1u << t) - 1u));
                if (pos >= m0 && pos < m0 + BM) srows[pos - m0] = b;
            }
            base += __popc(m);
        }
        if (t == 0) cnt_sh = base;
    }
    __syncthreads();
    if (m0 >= cnt_sh) return;   // uniform exit for empty tiles

    // ---- W cp.async roles: 1024 16B chunks per stage, 8 per thread ----
    const int wn_   = (t & 63) * 4;        // col within tile (0..252)
    const int khalf = t >> 6;              // 0/1
    const float* wbase = W + ((size_t)s * kD + kbase) * kOut + n0 + wn_;
    const int wsz = (n0 + wn_ + 3 < kOut) ? 16 : 0;   // zero-fill OOB n-tail

    auto issueW = [&](int st) {
        if (st < NSTG) {
            const int buf = st & 1;
            const float* wsrc = wbase + (size_t)st * BK * kOut;
            #pragma unroll
            for (int q = 0; q < 8; ++q) {
                const int k = 2 * q + khalf;
                cp16(smem_u32(&Ws[buf][k][wn_]), wsrc + (size_t)k * kOut, wsz);
            }
        }
        cp_commit();   // empty tail groups keep wait counts aligned
    };

    // ---- X roles: 128 k-quads per stage, 1 LDG.128 + 4 STS per thread ----
    const int xm_  = t >> 2;               // 0..31
    const int xk4  = (t & 3) * 4;          // k quad within stage
    const int xrow = srows[xm_];
    const float* xptr = (xrow >= 0) ? (x + (size_t)xrow * kD + kbase + xk4)
                                    : nullptr;
    float4 xr = make_float4(0.f, 0.f, 0.f, 0.f);

    issueW(0);
    issueW(1);
    if (xptr) xr = *reinterpret_cast<const float4*>(xptr);   // stage 0

    // ---- compute roles: rows [tm, tm+8), cols [tn, tn+8) ----
    const int tm = (t >> 5) * 8;           // uniform per warp -> broadcast LDS
    const int tn = (t & 31) * 8;

    unsigned long long acc[8][4];          // [m][n-pair]
    #pragma unroll
    for (int i = 0; i < 8; ++i)
        #pragma unroll
        for (int j = 0; j < 4; ++j) acc[i][j] = 0ull;

    for (int st = 0; st < NSTG; ++st) {
        const int buf = st & 1;
        cp_wait1();                         // W(st) arrived
        // transpose-store X(st)
        Xs[buf][xk4 + 0][xm_] = xr.x;
        Xs[buf][xk4 + 1][xm_] = xr.y;
        Xs[buf][xk4 + 2][xm_] = xr.z;
        Xs[buf][xk4 + 3][xm_] = xr.w;
        __syncthreads();
        // prefetch X(st+1) into registers
        if (st + 1 < NSTG && xptr)
            xr = *reinterpret_cast<const float4*>(xptr + (st + 1) * BK);

        #pragma unroll
        for (int kk = 0; kk < BK; ++kk) {
            const float4 xa = *reinterpret_cast<const float4*>(&Xs[buf][kk][tm]);
            const float4 xb = *reinterpret_cast<const float4*>(&Xs[buf][kk][tm + 4]);
            const ulonglong2 wA = *reinterpret_cast<const ulonglong2*>(&Ws[buf][kk][tn]);
            const ulonglong2 wB = *reinterpret_cast<const ulonglong2*>(&Ws[buf][kk][tn + 4]);
            const unsigned long long dx[8] = {
                dup2(xa.x), dup2(xa.y), dup2(xa.z), dup2(xa.w),
                dup2(xb.x), dup2(xb.y), dup2(xb.z), dup2(xb.w)};
            #pragma unroll
            for (int i = 0; i < 8; ++i) {
                ffma2(acc[i][0], dx[i], wA.x);
                ffma2(acc[i][1], dx[i], wA.y);
                ffma2(acc[i][2], dx[i], wB.x);
                ffma2(acc[i][3], dx[i], wB.y);
            }
        }
        __syncthreads();                    // all reads of Ws[buf] done
        issueW(st + 2);                     // refill into Ws[buf]
    }

    // ---- epilogue: write split partials (reduce adds bias) ----
    float* pbase = g_partial + (size_t)split * kB * kOut;
    #pragma unroll
    for (int i = 0; i < 8; ++i) {
        const int r = srows[tm + i];
        if (r < 0) continue;
        float v[8];
        #pragma unroll
        for (int j = 0; j < 4; ++j) unpack2(acc[i][j], v[2 * j], v[2 * j + 1]);
        float* prow = pbase + (size_t)r * kOut;
        const int n = n0 + tn;
        if (n + 3 < kOut)
            *reinterpret_cast<float4*>(prow + n) = make_float4(v[0], v[1], v[2], v[3]);
        if (n + 7 < kOut)
            *reinterpret_cast<float4*>(prow + n + 4) = make_float4(v[4], v[5], v[6], v[7]);
    }
}

// ---------------------------------------------------------------------------
// Reduce: out = sum of 16 split partials + per-subject bias.
// float2 granularity -> 128k threads (~27 warps/SM) to cover load latency.
// ---------------------------------------------------------------------------
__global__ __launch_bounds__(256) void reduce_kernel(
    const unsigned int* __restrict__ sid_words,
    const float* __restrict__ bias,   // [S, OUT]
    float* __restrict__ out)          // [B, OUT]
{
    __shared__ int i32_flag;
    if (threadIdx.x == 0) i32_flag = 0;
    __syncthreads();
    if (threadIdx.x < 128 && sid_words[2 * threadIdx.x + 1] != 0u)
        atomicOr(&i32_flag, 1);
    __syncthreads();

    const int q = blockIdx.x * blockDim.x + threadIdx.x;
    const int base = q * 2;
    if (base >= kB * kOut) return;
    const int b = base / kOut;
    const int n = base - b * kOut;        // kOut even: float2 stays in row
    const int sb = i32_flag ? (int)sid_words[b] : (int)sid_words[2 * b];

    float2 v = *reinterpret_cast<const float2*>(bias + (size_t)sb * kOut + n);
    #pragma unroll
    for (int sp = 0; sp < NSPLIT; ++sp) {
        const float2 p = *reinterpret_cast<const float2*>(
            g_partial + (size_t)sp * kB * kOut + base);
        v.x += p.x; v.y += p.y;
    }
    *reinterpret_cast<float2*>(out + base) = v;
}

extern "C" void kernel_launch(void* const* d_in, const int* in_sizes, int n_in,
                              void* d_out, int out_size) {
    const float*        x   = (const float*)d_in[0];
    const unsigned int* sid = (const unsigned int*)d_in[1];
    const float*        W   = (const float*)d_in[2];
    const float*        b   = (const float*)d_in[3];
    float*              out = (float*)d_out;

    dim3 grid(NTILES, kS, MT * NSPLIT);   // (4, 8, 64)
    gemm_kernel<<<grid, 128>>>(x, W, sid);
    const int nh = (kB * kOut) / 2;       // 128000 float2s
    reduce_kernel<<<(nh + 255) / 256, 256>>>(sid, b, out);
}

// round 7
// speedup vs baseline: 2.4823x; 1.1103x over previous
#include <cuda_runtime.h>
#include <cstdint>

namespace {
constexpr int kB   = 256;
constexpr int kD   = 2048;
constexpr int kS   = 8;
constexpr int kOut = 1000;

constexpr int BM = 32;                 // rows per m-tile
constexpr int BN = 256;                // cols per block
constexpr int BK = 16;                 // K per pipeline stage
constexpr int NSPLIT = 16;
constexpr int KSPLIT = kD / NSPLIT;    // 128
constexpr int NSTG   = KSPLIT / BK;    // 8 stages per block
constexpr int MT = 4;                  // m-tiles per subject (covers counts <= 128)
constexpr int XPAD = 36;               // X k-row stride (16B multiple, bank skew)
constexpr int NTILES = (kOut + BN - 1) / BN;  // 4
}

// Device scratch (allocations forbidden in kernel_launch)
__device__ float g_partial[NSPLIT * kB * kOut];   // 16 MB

// ---- packed f32x2 helpers ----
__device__ __forceinline__ void ffma2(unsigned long long& d,
                                      unsigned long long a, unsigned long long b) {
    asm("fma.rn.f32x2 %0, %1, %2, %0;" : "+l"(d) : "l"(a), "l"(b));
}
__device__ __forceinline__ unsigned long long dup2(float v) {
    unsigned long long r;
    asm("mov.b64 %0, {%1, %1};" : "=l"(r) : "f"(v));
    return r;
}
__device__ __forceinline__ void unpack2(unsigned long long v, float& lo, float& hi) {
    asm("mov.b64 {%0, %1}, %2;" : "=f"(lo), "=f"(hi) : "l"(v));
}

// ---- cp.async helpers ----
__device__ __forceinline__ unsigned smem_u32(const void* p) {
    return (unsigned)__cvta_generic_to_shared(p);
}
// cp.async with L2 evict_first policy: W is streamed exactly once, so keep it
// out of L2 and preserve residency for x and g_partial (read back by reduce).
__device__ __forceinline__ void cp16_ef(unsigned dst, const void* src, int src_sz,
                                        unsigned long long pol) {
    asm volatile("cp.async.cg.shared.global.L2::cache_hint [%0], [%1], 16, %2, %3;"
                 :: "r"(dst), "l"(src), "r"(src_sz), "l"(pol) : "memory");
}
__device__ __forceinline__ void cp_commit() {
    asm volatile("cp.async.commit_group;" ::: "memory");
}
__device__ __forceinline__ void cp_wait1() {
    asm volatile("cp.async.wait_group 1;" ::: "memory");
}

// ---------------------------------------------------------------------------
// GEMM: grid (n_tile=4, subject=8, mt(4)*split(16)=64), 128 threads.
// Thread tile 8m x 8n, but the 8 n-cols are two float4 groups 128 cols apart
// -> lane SMEM addresses stride 16B -> conflict-free LDS.128 (4 phases, was 8).
// W via cp.async(evict_first) 2-stage ring; X reg-staged LDG + transpose STS.
// ---------------------------------------------------------------------------
__global__ __launch_bounds__(128, 5) void gemm_kernel(
    const float* __restrict__ x,              // [B, D]
    const float* __restrict__ W,              // [S, D, OUT]
    const unsigned int* __restrict__ sid_words)
{
    const int s     = blockIdx.y;
    const int mt    = blockIdx.z & (MT - 1);
    const int split = blockIdx.z >> 2;        // MT = 4
    const int m0    = mt * BM;
    const int n0    = blockIdx.x * BN;
    const int kbase = split * KSPLIT;
    const int t     = threadIdx.x;
    const int lane  = t & 31;
    const int warp  = t >> 5;

    __shared__ __align__(16) float Xs[2][BK][XPAD];  // X tile [k][m]
    __shared__ __align__(16) float Ws[2][BK][BN];
    __shared__ int srows[BM];
    __shared__ int chunk_cnt[8];
    __shared__ int hi_flag;

    // ---- 4-warp parallel bucketing: ordered row list for subject s ----
    // int64-vs-int32 detection: for little-endian int64 ids in [0,8) all odd
    // 32-bit words of the first 256 words are zero.
    if (t < BM) srows[t] = -1;
    if (t == 0) hi_flag = 0;
    __syncthreads();

    const unsigned full = 0xFFFFFFFFu;
    const int b0 = (2 * warp) * 32 + lane;        // chunks 2w, 2w+1
    const int b1 = (2 * warp + 1) * 32 + lane;
    {
        const unsigned any_hi = sid_words[2 * b0 + 1] | sid_words[2 * b1 + 1];
        if (__any_sync(full, any_hi != 0u) && lane == 0) hi_flag = 1;
    }
    __syncthreads();
    const bool is_i32 = (hi_flag != 0);

    const int sb0 = is_i32 ? (int)sid_words[b0] : (int)sid_words[2 * b0];
    const int sb1 = is_i32 ? (int)sid_words[b1] : (int)sid_words[2 * b1];
    const unsigned msk0 = __ballot_sync(full, sb0 == s);
    const unsigned msk1 = __ballot_sync(full, sb1 == s);
    if (lane == 0) {
        chunk_cnt[2 * warp]     = __popc(msk0);
        chunk_cnt[2 * warp + 1] = __popc(msk1);
    }
    __syncthreads();

    int cnt = 0, base0 = 0;
    #pragma unroll
    for (int c = 0; c < 8; ++c) {
        if (c < 2 * warp) base0 += chunk_cnt[c];
        cnt += chunk_cnt[c];
    }
    if (m0 >= cnt) return;                        // uniform exit for empty tiles
    const int base1 = base0 + chunk_cnt[2 * warp];
    const unsigned below = (1u << lane) - 1u;
    if (sb0 == s) {
        const int pos = base0 + __popc(msk0 & below);
        if (pos >= m0 && pos < m0 + BM) srows[pos - m0] = b0;
    }
    if (sb1 == s) {
        const int pos = base1 + __popc(msk1 & below);
        if (pos >= m0 && pos < m0 + BM) srows[pos - m0] = b1;
    }
    __syncthreads();

    // ---- L2 evict_first policy for the single-use W stream ----
    unsigned long long pol;
    asm("createpolicy.fractional.L2::evict_first.b64 %0, 1.0;" : "=l"(pol));

    // ---- W cp.async roles: 1024 16B chunks per stage, 8 per thread ----
    const int wn_   = (t & 63) * 4;        // col within tile (0..252)
    const int khalf = t >> 6;              // 0/1
    const float* wbase = W + ((size_t)s * kD + kbase) * kOut + n0 + wn_;
    const int wsz = (n0 + wn_ + 3 < kOut) ? 16 : 0;   // zero-fill OOB n-tail

    auto issueW = [&](int st) {
        if (st < NSTG) {
            const int buf = st & 1;
            const float* wsrc = wbase + (size_t)st * BK * kOut;
            #pragma unroll
            for (int q = 0; q < 8; ++q) {
                const int k = 2 * q + khalf;
                cp16_ef(smem_u32(&Ws[buf][k][wn_]), wsrc + (size_t)k * kOut, wsz, pol);
            }
        }
        cp_commit();   // empty tail groups keep wait counts aligned
    };

    // ---- X roles: 128 k-quads per stage, 1 LDG.128 + 4 STS per thread ----
    const int xm_  = t >> 2;               // 0..31
    const int xk4  = (t & 3) * 4;          // k quad within stage
    const int xrow = srows[xm_];
    const float* xptr = (xrow >= 0) ? (x + (size_t)xrow * kD + kbase + xk4)
                                    : nullptr;
    float4 xr = make_float4(0.f, 0.f, 0.f, 0.f);

    issueW(0);
    issueW(1);
    if (xptr) xr = *reinterpret_cast<const float4*>(xptr);   // stage 0

    // ---- compute roles: rows [tm, tm+8); cols n0+ln..+3 and n0+128+ln..+3 ----
    const int tm = warp * 8;               // uniform per warp -> broadcast LDS
    const int ln = lane * 4;               // 16B lane stride -> conflict-free

    unsigned long long acc[8][4];          // [m][pairs: A0 A1 B0 B1]
    #pragma unroll
    for (int i = 0; i < 8; ++i)
        #pragma unroll
        for (int j = 0; j < 4; ++j) acc[i][j] = 0ull;

    for (int st = 0; st < NSTG; ++st) {
        const int buf = st & 1;
        cp_wait1();                         // W(st) arrived
        // transpose-store X(st)
        Xs[buf][xk4 + 0][xm_] = xr.x;
        Xs[buf][xk4 + 1][xm_] = xr.y;
        Xs[buf][xk4 + 2][xm_] = xr.z;
        Xs[buf][xk4 + 3][xm_] = xr.w;
        __syncthreads();
        // prefetch X(st+1) into registers
        if (st + 1 < NSTG && xptr)
            xr = *reinterpret_cast<const float4*>(xptr + (st + 1) * BK);

        #pragma unroll
        for (int kk = 0; kk < BK; ++kk) {
            const float4 xa = *reinterpret_cast<const float4*>(&Xs[buf][kk][tm]);
            const float4 xb = *reinterpret_cast<const float4*>(&Xs[buf][kk][tm + 4]);
            const ulonglong2 wA = *reinterpret_cast<const ulonglong2*>(&Ws[buf][kk][ln]);
            const ulonglong2 wB = *reinterpret_cast<const ulonglong2*>(&Ws[buf][kk][128 + ln]);
            const unsigned long long dx[8] = {
                dup2(xa.x), dup2(xa.y), dup2(xa.z), dup2(xa.w),
                dup2(xb.x), dup2(xb.y), dup2(xb.z), dup2(xb.w)};
            #pragma unroll
            for (int i = 0; i < 8; ++i) {
                ffma2(acc[i][0], dx[i], wA.x);
                ffma2(acc[i][1], dx[i], wA.y);
                ffma2(acc[i][2], dx[i], wB.x);
                ffma2(acc[i][3], dx[i], wB.y);
            }
        }
        __syncthreads();                    // all reads of Ws[buf] done
        issueW(st + 2);                     // refill into Ws[buf]
    }

    // ---- epilogue: write split partials (reduce adds bias) ----
    float* pbase = g_partial + (size_t)split * kB * kOut;
    const int nA = n0 + ln;
    const int nB = nA + 128;
    #pragma unroll
    for (int i = 0; i < 8; ++i) {
        const int r = srows[tm + i];
        if (r < 0) continue;
        float vA0, vA1, vA2, vA3, vB0, vB1, vB2, vB3;
        unpack2(acc[i][0], vA0, vA1);
        unpack2(acc[i][1], vA2, vA3);
        unpack2(acc[i][2], vB0, vB1);
        unpack2(acc[i][3], vB2, vB3);
        float* prow = pbase + (size_t)r * kOut;
        if (nA + 3 < kOut)
            *reinterpret_cast<float4*>(prow + nA) = make_float4(vA0, vA1, vA2, vA3);
        if (nB + 3 < kOut)
            *reinterpret_cast<float4*>(prow + nB) = make_float4(vB0, vB1, vB2, vB3);
    }
}

// ---------------------------------------------------------------------------
// Reduce: out = sum of 16 split partials + per-subject bias (float2, L2-hot).
// ---------------------------------------------------------------------------
__global__ __launch_bounds__(256) void reduce_kernel(
    const unsigned int* __restrict__ sid_words,
    const float* __restrict__ bias,   // [S, OUT]
    float* __restrict__ out)          // [B, OUT]
{
    __shared__ int i32_flag;
    if (threadIdx.x == 0) i32_flag = 0;
    __syncthreads();
    if (threadIdx.x < 128 && sid_words[2 * threadIdx.x + 1] != 0u)
        atomicOr(&i32_flag, 1);
    __syncthreads();

    const int q = blockIdx.x * blockDim.x + threadIdx.x;
    const int base = q * 2;
    if (base >= kB * kOut) return;
    const int b = base / kOut;
    const int n = base - b * kOut;        // kOut even: float2 stays in row
    const int sb = i32_flag ? (int)sid_words[b] : (int)sid_words[2 * b];

    float2 v = *reinterpret_cast<const float2*>(bias + (size_t)sb * kOut + n);
    #pragma unroll
    for (int sp = 0; sp < NSPLIT; ++sp) {
        const float2 p = *reinterpret_cast<const float2*>(
            g_partial + (size_t)sp * kB * kOut + base);
        v.x += p.x; v.y += p.y;
    }
    *reinterpret_cast<float2*>(out + base) = v;
}

extern "C" void kernel_launch(void* const* d_in, const int* in_sizes, int n_in,
                              void* d_out, int out_size) {
    const float*        x   = (const float*)d_in[0];
    const unsigned int* sid = (const unsigned int*)d_in[1];
    const float*        W   = (const float*)d_in[2];
    const float*        b   = (const float*)d_in[3];
    float*              out = (float*)d_out;

    dim3 grid(NTILES, kS, MT * NSPLIT);   // (4, 8, 64)
    gemm_kernel<<<grid, 128>>>(x, W, sid);
    const int nh = (kB * kOut) / 2;       // 128000 float2s
    reduce_kernel<<<(nh + 255) / 256, 256>>>(sid, b, out);
}